// round 2
// baseline (speedup 1.0000x reference)
#include <cuda_runtime.h>
#include <cstdint>

#define NUM_USERS 100000
#define NUM_ITEMS 50000
#define N_NODES   150000
#define EMB       64
#define BATCH     16384

// ---------------- scratch (static device allocations; no cudaMalloc) --------
__device__ float g_feat0[N_NODES * EMB];   // layer-0 features (concat embeddings)
__device__ float g_feat1[N_NODES * EMB];   // layer-1 output
__device__ float g_feat2[N_NODES * EMB];   // layer-2 output
__device__ float g_h    [N_NODES * EMB];   // SpMM accumulator (seeded with features)
__device__ float g_e    [BATCH * 384];     // gathered MLP input
__device__ float g_m1   [BATCH * 64];      // after relu(e@W1+b1)

// ---------------- kernel 1: feat0 = concat(uEmb, iEmb); g_h = feat0 ---------
__global__ void init_feat_kernel(const float4* __restrict__ uEmb,
                                 const float4* __restrict__ iEmb) {
    int idx = blockIdx.x * blockDim.x + threadIdx.x;   // over N_NODES*16 float4
    if (idx >= N_NODES * 16) return;
    float4 v = (idx < NUM_USERS * 16) ? uEmb[idx] : iEmb[idx - NUM_USERS * 16];
    ((float4*)g_feat0)[idx] = v;
    ((float4*)g_h)[idx]     = v;
}

// ---------------- kernel 2: h[row] += val * x[col]  (COO SpMM, v4 red) ------
__global__ void spmm_kernel(const int*   __restrict__ rows,
                            const int*   __restrict__ cols,
                            const float* __restrict__ vals,
                            const float* __restrict__ x,
                            float*       __restrict__ h,
                            int nnz) {
    long long idx = (long long)blockIdx.x * blockDim.x + threadIdx.x;
    int e = (int)(idx >> 4);          // 16 threads per nonzero (one float4 each)
    if (e >= nnz) return;
    int c   = (int)(idx & 15);
    int col = __ldg(cols + e);
    int row = __ldg(rows + e);
    float v = __ldg(vals + e);
    const float4 xv = *(const float4*)(x + (size_t)col * EMB + c * 4);
    float4 r;
    r.x = v * xv.x; r.y = v * xv.y; r.z = v * xv.z; r.w = v * xv.w;
    float* dst = h + (size_t)row * EMB + c * 4;
    asm volatile("red.global.add.v4.f32 [%0], {%1,%2,%3,%4};"
                 :: "l"(dst), "f"(r.x), "f"(r.y), "f"(r.z), "f"(r.w)
                 : "memory");
}

// ---------------- kernel 3: out = relu(h @ W[64,64] + b); warp per row ------
__global__ __launch_bounds__(256)
void gemm64_relu_kernel(const float* __restrict__ h,
                        const float* __restrict__ W,
                        const float* __restrict__ b,
                        float* __restrict__ outA,
                        float* __restrict__ outB,   // optional second copy (next h seed)
                        int nrows) {
    __shared__ float sW[64 * 64];
    __shared__ float sb[64];
    int tid = threadIdx.x;
    #pragma unroll
    for (int i = tid; i < 64 * 64; i += 256) sW[i] = W[i];
    if (tid < 64) sb[tid] = b[tid];
    __syncthreads();

    int lane = tid & 31;
    int row  = blockIdx.x * 8 + (tid >> 5);
    if (row >= nrows) return;

    const float* hr = h + (size_t)row * 64;
    float a0 = hr[lane], a1 = hr[lane + 32];
    float acc0 = sb[lane], acc1 = sb[lane + 32];
    #pragma unroll
    for (int k = 0; k < 32; k++) {
        float hk = __shfl_sync(0xffffffffu, a0, k);
        acc0 += hk * sW[k * 64 + lane];
        acc1 += hk * sW[k * 64 + lane + 32];
    }
    #pragma unroll
    for (int k = 0; k < 32; k++) {
        float hk = __shfl_sync(0xffffffffu, a1, k);
        acc0 += hk * sW[(k + 32) * 64 + lane];
        acc1 += hk * sW[(k + 32) * 64 + lane + 32];
    }
    acc0 = fmaxf(acc0, 0.f);
    acc1 = fmaxf(acc1, 0.f);
    float* o = outA + (size_t)row * 64;
    o[lane] = acc0; o[lane + 32] = acc1;
    if (outB) {
        float* o2 = outB + (size_t)row * 64;
        o2[lane] = acc0; o2[lane + 32] = acc1;
    }
}

// ---------------- kernel 4: gather e[b] = [final[u] | final[i+U]] -----------
__global__ void gather_kernel(const int* __restrict__ userIdx,
                              const int* __restrict__ itemIdx) {
    int idx = blockIdx.x * blockDim.x + threadIdx.x;   // over BATCH*96 float4
    if (idx >= BATCH * 96) return;
    int b  = idx / 96;
    int c  = idx - b * 96;          // float4 index within 384-dim row
    int half = c / 48;              // 0: user half, 1: item half
    int cc   = c - half * 48;       // within 192 dims (48 float4)
    int seg  = cc >> 4;             // which feature buffer (0,1,2)
    int off  = cc & 15;             // float4 within 64 dims
    int node = half ? (__ldg(itemIdx + b) + NUM_USERS) : __ldg(userIdx + b);
    const float* src = (seg == 0) ? g_feat0 : (seg == 1) ? g_feat1 : g_feat2;
    float4 v = *(const float4*)(src + (size_t)node * 64 + off * 4);
    *(float4*)(g_e + (size_t)b * 384 + c * 4) = v;
}

// ---------------- kernel 5: m1 = relu(e[B,384] @ W1[384,64] + b1) -----------
__global__ __launch_bounds__(256)
void mlp1_kernel(const float* __restrict__ W1, const float* __restrict__ b1) {
    __shared__ float sW[64 * 64];
    int tid  = threadIdx.x;
    int lane = tid & 31, wid = tid >> 5;
    int base_row = blockIdx.x * 64 + wid * 8;

    float bb0 = b1[lane], bb1 = b1[lane + 32];
    float acc0[8], acc1[8];
    #pragma unroll
    for (int r = 0; r < 8; r++) { acc0[r] = bb0; acc1[r] = bb1; }

    for (int kk = 0; kk < 6; kk++) {
        __syncthreads();
        #pragma unroll
        for (int i = tid; i < 64 * 64; i += 256) sW[i] = W1[kk * 64 * 64 + i];
        __syncthreads();
        #pragma unroll
        for (int r = 0; r < 8; r++) {
            const float* er = g_e + (size_t)(base_row + r) * 384 + kk * 64;
            float a0 = er[lane], a1 = er[lane + 32];
            #pragma unroll
            for (int k = 0; k < 32; k++) {
                float hk = __shfl_sync(0xffffffffu, a0, k);
                acc0[r] += hk * sW[k * 64 + lane];
                acc1[r] += hk * sW[k * 64 + lane + 32];
            }
            #pragma unroll
            for (int k = 0; k < 32; k++) {
                float hk = __shfl_sync(0xffffffffu, a1, k);
                acc0[r] += hk * sW[(k + 32) * 64 + lane];
                acc1[r] += hk * sW[(k + 32) * 64 + lane + 32];
            }
        }
    }
    #pragma unroll
    for (int r = 0; r < 8; r++) {
        float* o = g_m1 + (size_t)(base_row + r) * 64;
        o[lane]      = fmaxf(acc0[r], 0.f);
        o[lane + 32] = fmaxf(acc1[r], 0.f);
    }
}

// ---------------- kernel 6: out = (m1 @ W2 + b2) @ W3 + b3 ------------------
__global__ __launch_bounds__(256)
void mlp23_kernel(const float* __restrict__ W2, const float* __restrict__ b2,
                  const float* __restrict__ W3, const float* __restrict__ b3,
                  float* __restrict__ out) {
    __shared__ float sW2[64 * 32];
    __shared__ float sb2[32];
    __shared__ float sW3[32];
    __shared__ float sb3;
    int tid = threadIdx.x;
    #pragma unroll
    for (int i = tid; i < 64 * 32; i += 256) sW2[i] = W2[i];
    if (tid < 32) { sb2[tid] = b2[tid]; sW3[tid] = W3[tid]; }
    if (tid == 0) sb3 = b3[0];
    __syncthreads();

    int lane = tid & 31;
    int row  = blockIdx.x * 8 + (tid >> 5);
    if (row >= BATCH) return;

    const float* mr = g_m1 + (size_t)row * 64;
    float a0 = mr[lane], a1 = mr[lane + 32];
    float acc = sb2[lane];                 // lane = output column j (0..31)
    #pragma unroll
    for (int k = 0; k < 32; k++) {
        float hk = __shfl_sync(0xffffffffu, a0, k);
        acc += hk * sW2[k * 32 + lane];
    }
    #pragma unroll
    for (int k = 0; k < 32; k++) {
        float hk = __shfl_sync(0xffffffffu, a1, k);
        acc += hk * sW2[(k + 32) * 32 + lane];
    }
    float p = acc * sW3[lane];             // no ReLU after W2 (matches reference)
    #pragma unroll
    for (int off = 16; off > 0; off >>= 1)
        p += __shfl_xor_sync(0xffffffffu, p, off);
    if (lane == 0) out[row] = p + sb3;
}

// ---------------- launch ----------------------------------------------------
extern "C" void kernel_launch(void* const* d_in, const int* in_sizes, int n_in,
                              void* d_out, int out_size) {
    const int*   userIdx = (const int*)  d_in[0];
    const int*   itemIdx = (const int*)  d_in[1];
    const int*   lapRows = (const int*)  d_in[2];
    const int*   lapCols = (const int*)  d_in[3];
    const float* lapVals = (const float*)d_in[4];
    const float* uEmb    = (const float*)d_in[5];
    const float* iEmb    = (const float*)d_in[6];
    const float* gW0     = (const float*)d_in[7];
    const float* gb0     = (const float*)d_in[8];
    const float* gW1     = (const float*)d_in[9];
    const float* gb1     = (const float*)d_in[10];
    const float* W1      = (const float*)d_in[11];
    const float* b1      = (const float*)d_in[12];
    const float* W2      = (const float*)d_in[13];
    const float* b2      = (const float*)d_in[14];
    const float* W3      = (const float*)d_in[15];
    const float* b3      = (const float*)d_in[16];
    float* out = (float*)d_out;

    const int nnz = in_sizes[2];

    float *feat0, *feat1, *feat2, *h;
    cudaGetSymbolAddress((void**)&feat0, g_feat0);
    cudaGetSymbolAddress((void**)&feat1, g_feat1);
    cudaGetSymbolAddress((void**)&feat2, g_feat2);
    cudaGetSymbolAddress((void**)&h,     g_h);

    // 1. feat0 = concat(uEmb, iEmb); h = feat0  (folds the +features self-loop)
    {
        int total = N_NODES * 16;
        init_feat_kernel<<<(total + 255) / 256, 256>>>((const float4*)uEmb,
                                                       (const float4*)iEmb);
    }

    // 2. layer 1: h += L @ feat0 ; feat1 = relu(h @ gW0 + gb0); h = feat1
    {
        long long t = (long long)nnz * 16;
        int blocks = (int)((t + 255) / 256);
        spmm_kernel<<<blocks, 256>>>(lapRows, lapCols, lapVals, feat0, h, nnz);
        gemm64_relu_kernel<<<(N_NODES + 7) / 8, 256>>>(h, gW0, gb0, feat1, h, N_NODES);
    }

    // 3. layer 2: h += L @ feat1 ; feat2 = relu(h @ gW1 + gb1)
    {
        long long t = (long long)nnz * 16;
        int blocks = (int)((t + 255) / 256);
        spmm_kernel<<<blocks, 256>>>(lapRows, lapCols, lapVals, feat1, h, nnz);
        gemm64_relu_kernel<<<(N_NODES + 7) / 8, 256>>>(h, gW1, gb1, feat2, nullptr, N_NODES);
    }

    // 4. gather e = [final[user] | final[item+U]]
    gather_kernel<<<(BATCH * 96 + 255) / 256, 256>>>(userIdx, itemIdx);

    // 5. m1 = relu(e @ W1 + b1)
    mlp1_kernel<<<BATCH / 64, 256>>>(W1, b1);

    // 6. out = (m1 @ W2 + b2) @ W3 + b3
    mlp23_kernel<<<(BATCH + 7) / 8, 256>>>(W2, b2, W3, b3, out);
}

// round 3
// speedup vs baseline: 1.0377x; 1.0377x over previous
#include <cuda_runtime.h>
#include <cstdint>

#define NUM_USERS 100000
#define NUM_ITEMS 50000
#define N_NODES   150000
#define EMB       64
#define BATCH     16384

// ---------------- scratch (static device allocations; no cudaMalloc) --------
__device__ float g_feat0[N_NODES * EMB];   // layer-0 features (concat embeddings)
__device__ float g_feat1[N_NODES * EMB];   // layer-1 output
__device__ float g_feat2[N_NODES * EMB];   // layer-2 output
__device__ float g_h    [N_NODES * EMB];   // SpMM accumulator (seeded with features)

// ---------------- kernel 1: feat0 = concat(uEmb, iEmb); g_h = feat0 ---------
__global__ void init_feat_kernel(const float4* __restrict__ uEmb,
                                 const float4* __restrict__ iEmb) {
    int idx = blockIdx.x * blockDim.x + threadIdx.x;   // over N_NODES*16 float4
    if (idx >= N_NODES * 16) return;
    float4 v = (idx < NUM_USERS * 16) ? uEmb[idx] : iEmb[idx - NUM_USERS * 16];
    ((float4*)g_feat0)[idx] = v;
    ((float4*)g_h)[idx]     = v;
}

// ---------------- kernel 2: h[row] += val * x[col]  (COO SpMM) --------------
// 16 lanes per edge (one float4 each); 4 edges per thread, strided, so each
// thread keeps 4 independent gather loads + 4 reds in flight (MLP=4).
#define SPMM_EPT 4
__global__ __launch_bounds__(256)
void spmm_kernel(const int*   __restrict__ rows,
                 const int*   __restrict__ cols,
                 const float* __restrict__ vals,
                 const float* __restrict__ x,
                 float*       __restrict__ h,
                 int nnz, int stride) {
    long long t = (long long)blockIdx.x * blockDim.x + threadIdx.x;
    int slot = (int)(t >> 4);
    if (slot >= stride) return;
    int c = (int)(t & 15);

    int   e[SPMM_EPT];
    bool  p[SPMM_EPT];
    int   row[SPMM_EPT], col[SPMM_EPT];
    float v[SPMM_EPT];
    #pragma unroll
    for (int i = 0; i < SPMM_EPT; i++) {
        e[i] = slot + i * stride;
        p[i] = (e[i] < nnz);
    }
    #pragma unroll
    for (int i = 0; i < SPMM_EPT; i++) {
        if (p[i]) {
            col[i] = __ldg(cols + e[i]);
            row[i] = __ldg(rows + e[i]);
            v[i]   = __ldg(vals + e[i]);
        }
    }
    float4 xv[SPMM_EPT];
    #pragma unroll
    for (int i = 0; i < SPMM_EPT; i++) {
        if (p[i])
            xv[i] = *(const float4*)(x + (size_t)col[i] * EMB + c * 4);
    }
    #pragma unroll
    for (int i = 0; i < SPMM_EPT; i++) {
        if (p[i]) {
            float4 r;
            r.x = v[i] * xv[i].x; r.y = v[i] * xv[i].y;
            r.z = v[i] * xv[i].z; r.w = v[i] * xv[i].w;
            float* dst = h + (size_t)row[i] * EMB + c * 4;
            asm volatile("red.global.add.v4.f32 [%0], {%1,%2,%3,%4};"
                         :: "l"(dst), "f"(r.x), "f"(r.y), "f"(r.z), "f"(r.w)
                         : "memory");
        }
    }
}

// ---------------- kernel 3: out = relu(h @ W[64,64] + b); warp per row ------
__global__ __launch_bounds__(256)
void gemm64_relu_kernel(const float* __restrict__ h,
                        const float* __restrict__ W,
                        const float* __restrict__ b,
                        float* __restrict__ outA,
                        float* __restrict__ outB,   // optional second copy (next h seed)
                        int nrows) {
    __shared__ float sW[64 * 64];
    __shared__ float sb[64];
    int tid = threadIdx.x;
    #pragma unroll
    for (int i = tid; i < 64 * 64; i += 256) sW[i] = W[i];
    if (tid < 64) sb[tid] = b[tid];
    __syncthreads();

    int lane = tid & 31;
    int row  = blockIdx.x * 8 + (tid >> 5);
    if (row >= nrows) return;

    const float* hr = h + (size_t)row * 64;
    float a0 = hr[lane], a1 = hr[lane + 32];
    float acc0 = sb[lane], acc1 = sb[lane + 32];
    #pragma unroll
    for (int k = 0; k < 32; k++) {
        float hk = __shfl_sync(0xffffffffu, a0, k);
        acc0 += hk * sW[k * 64 + lane];
        acc1 += hk * sW[k * 64 + lane + 32];
    }
    #pragma unroll
    for (int k = 0; k < 32; k++) {
        float hk = __shfl_sync(0xffffffffu, a1, k);
        acc0 += hk * sW[(k + 32) * 64 + lane];
        acc1 += hk * sW[(k + 32) * 64 + lane + 32];
    }
    acc0 = fmaxf(acc0, 0.f);
    acc1 = fmaxf(acc1, 0.f);
    float* o = outA + (size_t)row * 64;
    o[lane] = acc0; o[lane + 32] = acc1;
    if (outB) {
        float* o2 = outB + (size_t)row * 64;
        o2[lane] = acc0; o2[lane + 32] = acc1;
    }
}

// ---------------- kernel 4: fused gather + full MLP -------------------------
// e[b] = [final[u] | final[i+U]] where final = [feat0|feat1|feat2] per node.
// Stage 1: m1 = relu(e @ W1[384,64] + b1)   (warp holds m1 row across lanes)
// Stage 2: m2 = m1 @ W2[64,32] + b2          (lane = output col)
// Stage 3: out = m2 @ W3[32,1] + b3          (butterfly reduce)
__global__ __launch_bounds__(256)
void mlp_fused_kernel(const int*   __restrict__ userIdx,
                      const int*   __restrict__ itemIdx,
                      const float* __restrict__ W1, const float* __restrict__ b1,
                      const float* __restrict__ W2, const float* __restrict__ b2,
                      const float* __restrict__ W3, const float* __restrict__ b3,
                      float* __restrict__ out) {
    __shared__ float sW[64 * 64];     // current W1 segment
    __shared__ float sW2[64 * 32];
    __shared__ float sb2[32];
    __shared__ float sW3[32];
    __shared__ float sb3;

    int tid  = threadIdx.x;
    int lane = tid & 31, wid = tid >> 5;
    int base_row = blockIdx.x * 64 + wid * 8;

    #pragma unroll
    for (int i = tid; i < 64 * 32; i += 256) sW2[i] = W2[i];
    if (tid < 32) { sb2[tid] = b2[tid]; sW3[tid] = W3[tid]; }
    if (tid == 0) sb3 = b3[0];

    // node indices for this warp's 8 rows
    int unode[8], inode[8];
    #pragma unroll
    for (int r = 0; r < 8; r++) {
        unode[r] = __ldg(userIdx + base_row + r);
        inode[r] = __ldg(itemIdx + base_row + r) + NUM_USERS;
    }

    float bb0 = __ldg(b1 + lane), bb1 = __ldg(b1 + lane + 32);
    float acc0[8], acc1[8];
    #pragma unroll
    for (int r = 0; r < 8; r++) { acc0[r] = bb0; acc1[r] = bb1; }

    #pragma unroll
    for (int kk = 0; kk < 6; kk++) {
        __syncthreads();
        #pragma unroll
        for (int i = tid; i < 64 * 64; i += 256) sW[i] = W1[kk * 64 * 64 + i];
        __syncthreads();

        int seg = (kk < 3) ? kk : kk - 3;
        const float* src = (seg == 0) ? g_feat0 : (seg == 1) ? g_feat1 : g_feat2;

        #pragma unroll
        for (int r = 0; r < 8; r++) {
            int node = (kk < 3) ? unode[r] : inode[r];
            const float* er = src + (size_t)node * 64;
            float a0 = er[lane], a1 = er[lane + 32];
            #pragma unroll
            for (int k = 0; k < 32; k++) {
                float hk = __shfl_sync(0xffffffffu, a0, k);
                acc0[r] += hk * sW[k * 64 + lane];
                acc1[r] += hk * sW[k * 64 + lane + 32];
            }
            #pragma unroll
            for (int k = 0; k < 32; k++) {
                float hk = __shfl_sync(0xffffffffu, a1, k);
                acc0[r] += hk * sW[(k + 32) * 64 + lane];
                acc1[r] += hk * sW[(k + 32) * 64 + lane + 32];
            }
        }
    }

    // stages 2+3, entirely in-warp
    #pragma unroll
    for (int r = 0; r < 8; r++) {
        float a0 = fmaxf(acc0[r], 0.f);     // m1[lane]
        float a1 = fmaxf(acc1[r], 0.f);     // m1[lane+32]
        float acc = sb2[lane];              // lane = output col j (0..31)
        #pragma unroll
        for (int k = 0; k < 32; k++) {
            float hk = __shfl_sync(0xffffffffu, a0, k);
            acc += hk * sW2[k * 32 + lane];
        }
        #pragma unroll
        for (int k = 0; k < 32; k++) {
            float hk = __shfl_sync(0xffffffffu, a1, k);
            acc += hk * sW2[(k + 32) * 32 + lane];
        }
        float p = acc * sW3[lane];          // no ReLU after W2 (matches reference)
        #pragma unroll
        for (int off = 16; off > 0; off >>= 1)
            p += __shfl_xor_sync(0xffffffffu, p, off);
        if (lane == 0) out[base_row + r] = p + sb3;
    }
}

// ---------------- launch ----------------------------------------------------
extern "C" void kernel_launch(void* const* d_in, const int* in_sizes, int n_in,
                              void* d_out, int out_size) {
    const int*   userIdx = (const int*)  d_in[0];
    const int*   itemIdx = (const int*)  d_in[1];
    const int*   lapRows = (const int*)  d_in[2];
    const int*   lapCols = (const int*)  d_in[3];
    const float* lapVals = (const float*)d_in[4];
    const float* uEmb    = (const float*)d_in[5];
    const float* iEmb    = (const float*)d_in[6];
    const float* gW0     = (const float*)d_in[7];
    const float* gb0     = (const float*)d_in[8];
    const float* gW1     = (const float*)d_in[9];
    const float* gb1     = (const float*)d_in[10];
    const float* W1      = (const float*)d_in[11];
    const float* b1      = (const float*)d_in[12];
    const float* W2      = (const float*)d_in[13];
    const float* b2      = (const float*)d_in[14];
    const float* W3      = (const float*)d_in[15];
    const float* b3      = (const float*)d_in[16];
    float* out = (float*)d_out;

    const int nnz = in_sizes[2];

    float *feat0, *feat1, *feat2, *h;
    cudaGetSymbolAddress((void**)&feat0, g_feat0);
    cudaGetSymbolAddress((void**)&feat1, g_feat1);
    cudaGetSymbolAddress((void**)&feat2, g_feat2);
    cudaGetSymbolAddress((void**)&h,     g_h);

    // 1. feat0 = concat(uEmb, iEmb); h = feat0  (folds the +features self-loop)
    {
        int total = N_NODES * 16;
        init_feat_kernel<<<(total + 255) / 256, 256>>>((const float4*)uEmb,
                                                       (const float4*)iEmb);
    }

    const int stride = (nnz + SPMM_EPT - 1) / SPMM_EPT;
    const long long spmm_threads = (long long)stride * 16;
    const int spmm_blocks = (int)((spmm_threads + 255) / 256);

    // 2. layer 1: h += L @ feat0 ; feat1 = relu(h @ gW0 + gb0); h = feat1
    spmm_kernel<<<spmm_blocks, 256>>>(lapRows, lapCols, lapVals, feat0, h, nnz, stride);
    gemm64_relu_kernel<<<(N_NODES + 7) / 8, 256>>>(h, gW0, gb0, feat1, h, N_NODES);

    // 3. layer 2: h += L @ feat1 ; feat2 = relu(h @ gW1 + gb1)
    spmm_kernel<<<spmm_blocks, 256>>>(lapRows, lapCols, lapVals, feat1, h, nnz, stride);
    gemm64_relu_kernel<<<(N_NODES + 7) / 8, 256>>>(h, gW1, gb1, feat2, nullptr, N_NODES);

    // 4. fused gather + 3-layer MLP
    mlp_fused_kernel<<<BATCH / 64, 256>>>(userIdx, itemIdx,
                                          W1, b1, W2, b2, W3, b3, out);
}

// round 4
// speedup vs baseline: 1.6818x; 1.6207x over previous
#include <cuda_runtime.h>
#include <cstdint>

#define NUM_USERS 100000
#define NUM_ITEMS 50000
#define N_NODES   150000
#define EMB       64
#define BATCH     16384
#define NNZ_MAX   2400000
#define NB_SCAN   ((N_NODES + 255) / 256)

// ---------------- scratch (static device allocations; no cudaMalloc) --------
__device__ float g_feat0[N_NODES * EMB];
__device__ float g_feat1[N_NODES * EMB];
__device__ float g_feat2[N_NODES * EMB];
__device__ int   g_cnt[N_NODES];
__device__ int   g_rowptr[N_NODES + 1];
__device__ int   g_cursor[N_NODES];
__device__ int   g_part[NB_SCAN];
__device__ int   g_partscan[NB_SCAN];
__device__ int2  g_edges[NNZ_MAX];          // sorted-by-row (col, val_bits)

// ---------------- kernel: feat0 = concat(uEmb, iEmb) ------------------------
__global__ void init_feat_kernel(const float4* __restrict__ uEmb,
                                 const float4* __restrict__ iEmb) {
    int idx = blockIdx.x * blockDim.x + threadIdx.x;   // over N_NODES*16 float4
    if (idx >= N_NODES * 16) return;
    ((float4*)g_feat0)[idx] =
        (idx < NUM_USERS * 16) ? uEmb[idx] : iEmb[idx - NUM_USERS * 16];
}

// ---------------- CSR build: histogram + scan + scatter ---------------------
__global__ void zero_cnt_kernel() {
    int i = blockIdx.x * 256 + threadIdx.x;
    if (i < N_NODES) g_cnt[i] = 0;
}

__global__ void hist_kernel(const int* __restrict__ rows, int nnz) {
    int e = blockIdx.x * 256 + threadIdx.x;
    if (e < nnz) atomicAdd(&g_cnt[rows[e]], 1);
}

__global__ void scan1_kernel() {
    __shared__ int sm[256];
    int t = threadIdx.x;
    int i = blockIdx.x * 256 + t;
    int c = (i < N_NODES) ? g_cnt[i] : 0;
    sm[t] = c;
    __syncthreads();
    #pragma unroll
    for (int off = 1; off < 256; off <<= 1) {
        int v = (t >= off) ? sm[t - off] : 0;
        __syncthreads();
        sm[t] += v;
        __syncthreads();
    }
    if (i < N_NODES) g_rowptr[i] = sm[t] - c;      // block-local exclusive
    if (t == 255) g_part[blockIdx.x] = sm[255];    // block total
}

__global__ void scan2_kernel() {
    __shared__ int sm[1024];
    int t = threadIdx.x;
    int c = (t < NB_SCAN) ? g_part[t] : 0;
    sm[t] = c;
    __syncthreads();
    #pragma unroll
    for (int off = 1; off < 1024; off <<= 1) {
        int v = (t >= off) ? sm[t - off] : 0;
        __syncthreads();
        sm[t] += v;
        __syncthreads();
    }
    if (t < NB_SCAN) g_partscan[t] = sm[t] - c;    // exclusive
}

__global__ void scan3_kernel(int nnz) {
    int t = threadIdx.x;
    int i = blockIdx.x * 256 + t;
    if (i < N_NODES) {
        int v = g_rowptr[i] + g_partscan[blockIdx.x];
        g_rowptr[i] = v;
        g_cursor[i] = v;
    }
    if (i == 0) g_rowptr[N_NODES] = nnz;
}

__global__ void scatter_kernel(const int*   __restrict__ rows,
                               const int*   __restrict__ cols,
                               const float* __restrict__ vals, int nnz) {
    int e = blockIdx.x * 256 + threadIdx.x;
    if (e >= nnz) return;
    int r = rows[e];
    int pos = atomicAdd(&g_cursor[r], 1);
    g_edges[pos] = make_int2(cols[e], __float_as_int(vals[e]));
}

// ---------------- fused layer: feat_out = relu((L@x + x) @ W + b) -----------
// One warp handles 4 consecutive rows. CSR accumulation in registers (no g_h,
// no atomics), then shuffle-GEMM epilogue with weight LDS shared across the
// 4 rows (4 KB smem read per row instead of 16 KB).
__global__ __launch_bounds__(256)
void spmm_gemm_kernel(const float* __restrict__ x,
                      const float* __restrict__ W,
                      const float* __restrict__ b,
                      float* __restrict__ out, int nrows) {
    __shared__ float2 sW[64 * 32];    // sW[k*32+j] = (W[k][j], W[k][j+32])
    __shared__ float  sb[64];
    int tid = threadIdx.x;
    #pragma unroll
    for (int i = tid; i < 2048; i += 256) {
        int k = i >> 5, j = i & 31;
        sW[i] = make_float2(W[k * 64 + j], W[k * 64 + j + 32]);
    }
    if (tid < 64) sb[tid] = b[tid];
    __syncthreads();

    int lane = tid & 31;
    int warp = tid >> 5;
    int r0 = (blockIdx.x * 8 + warp) * 4;

    float acc0[4], acc1[4];
    #pragma unroll
    for (int rr = 0; rr < 4; rr++) {
        int row = r0 + rr;
        if (row >= nrows) { acc0[rr] = 0.f; acc1[rr] = 0.f; continue; }
        const float* xr = x + (size_t)row * 64;
        float a0 = xr[lane], a1 = xr[lane + 32];           // self loop
        int s = g_rowptr[row], e = g_rowptr[row + 1];
        int i = s;
        for (; i + 4 <= e; i += 4) {
            int2 c0 = g_edges[i],     c1 = g_edges[i + 1];
            int2 c2 = g_edges[i + 2], c3 = g_edges[i + 3];
            float x00 = x[(size_t)c0.x * 64 + lane], x01 = x[(size_t)c0.x * 64 + lane + 32];
            float x10 = x[(size_t)c1.x * 64 + lane], x11 = x[(size_t)c1.x * 64 + lane + 32];
            float x20 = x[(size_t)c2.x * 64 + lane], x21 = x[(size_t)c2.x * 64 + lane + 32];
            float x30 = x[(size_t)c3.x * 64 + lane], x31 = x[(size_t)c3.x * 64 + lane + 32];
            a0 += __int_as_float(c0.y) * x00;  a1 += __int_as_float(c0.y) * x01;
            a0 += __int_as_float(c1.y) * x10;  a1 += __int_as_float(c1.y) * x11;
            a0 += __int_as_float(c2.y) * x20;  a1 += __int_as_float(c2.y) * x21;
            a0 += __int_as_float(c3.y) * x30;  a1 += __int_as_float(c3.y) * x31;
        }
        for (; i < e; i++) {
            int2 c = g_edges[i];
            a0 += __int_as_float(c.y) * x[(size_t)c.x * 64 + lane];
            a1 += __int_as_float(c.y) * x[(size_t)c.x * 64 + lane + 32];
        }
        acc0[rr] = a0; acc1[rr] = a1;
    }

    // GEMM epilogue: out[c] = relu(b[c] + sum_k h[k] * W[k][c])
    float o0[4], o1[4];
    #pragma unroll
    for (int rr = 0; rr < 4; rr++) { o0[rr] = sb[lane]; o1[rr] = sb[lane + 32]; }
    #pragma unroll
    for (int k = 0; k < 32; k++) {
        float2 w = sW[k * 32 + lane];
        #pragma unroll
        for (int rr = 0; rr < 4; rr++) {
            float hk = __shfl_sync(0xffffffffu, acc0[rr], k);
            o0[rr] += hk * w.x;  o1[rr] += hk * w.y;
        }
    }
    #pragma unroll
    for (int k = 0; k < 32; k++) {
        float2 w = sW[(k + 32) * 32 + lane];
        #pragma unroll
        for (int rr = 0; rr < 4; rr++) {
            float hk = __shfl_sync(0xffffffffu, acc1[rr], k);
            o0[rr] += hk * w.x;  o1[rr] += hk * w.y;
        }
    }
    #pragma unroll
    for (int rr = 0; rr < 4; rr++) {
        int row = r0 + rr;
        if (row >= nrows) break;
        float* op = out + (size_t)row * 64;
        op[lane]      = fmaxf(o0[rr], 0.f);
        op[lane + 32] = fmaxf(o1[rr], 0.f);
    }
}

// ---------------- fused gather + 3-layer MLP --------------------------------
__global__ __launch_bounds__(256)
void mlp_fused_kernel(const int*   __restrict__ userIdx,
                      const int*   __restrict__ itemIdx,
                      const float* __restrict__ W1, const float* __restrict__ b1,
                      const float* __restrict__ W2, const float* __restrict__ b2,
                      const float* __restrict__ W3, const float* __restrict__ b3,
                      float* __restrict__ out) {
    __shared__ float2 sW[64 * 32];    // current W1 segment, paired cols
    __shared__ float  sW2[64 * 32];
    __shared__ float  sb2[32], sW3[32];
    __shared__ float  sb3;

    int tid = threadIdx.x, lane = tid & 31, warp = tid >> 5;
    #pragma unroll
    for (int i = tid; i < 2048; i += 256) sW2[i] = W2[i];
    if (tid < 32) { sb2[tid] = b2[tid]; sW3[tid] = W3[tid]; }
    if (tid == 0) sb3 = b3[0];

    int base = blockIdx.x * 64 + warp * 8;
    int unode[8], inode[8];
    #pragma unroll
    for (int r = 0; r < 8; r++) {
        unode[r] = __ldg(userIdx + base + r);
        inode[r] = __ldg(itemIdx + base + r) + NUM_USERS;
    }

    float bb0 = __ldg(b1 + lane), bb1 = __ldg(b1 + lane + 32);
    float acc0[8], acc1[8];
    #pragma unroll
    for (int r = 0; r < 8; r++) { acc0[r] = bb0; acc1[r] = bb1; }

    #pragma unroll
    for (int kk = 0; kk < 6; kk++) {
        __syncthreads();
        #pragma unroll
        for (int i = tid; i < 2048; i += 256) {
            int k = i >> 5, j = i & 31;
            sW[i] = make_float2(W1[(kk * 64 + k) * 64 + j],
                                W1[(kk * 64 + k) * 64 + j + 32]);
        }
        __syncthreads();

        int seg = (kk < 3) ? kk : kk - 3;
        const float* src = (seg == 0) ? g_feat0 : (seg == 1) ? g_feat1 : g_feat2;

        float a0[8], a1[8];
        #pragma unroll
        for (int r = 0; r < 8; r++) {
            int node = (kk < 3) ? unode[r] : inode[r];
            const float* er = src + (size_t)node * 64;
            a0[r] = er[lane]; a1[r] = er[lane + 32];
        }
        #pragma unroll
        for (int k = 0; k < 32; k++) {
            float2 w = sW[k * 32 + lane];
            #pragma unroll
            for (int r = 0; r < 8; r++) {
                float hk = __shfl_sync(0xffffffffu, a0[r], k);
                acc0[r] += hk * w.x;  acc1[r] += hk * w.y;
            }
        }
        #pragma unroll
        for (int k = 0; k < 32; k++) {
            float2 w = sW[(k + 32) * 32 + lane];
            #pragma unroll
            for (int r = 0; r < 8; r++) {
                float hk = __shfl_sync(0xffffffffu, a1[r], k);
                acc0[r] += hk * w.x;  acc1[r] += hk * w.y;
            }
        }
    }

    // stages 2+3, in-warp
    #pragma unroll
    for (int r = 0; r < 8; r++) {
        float m0  = fmaxf(acc0[r], 0.f);
        float m1v = fmaxf(acc1[r], 0.f);
        float acc = sb2[lane];                 // lane = output col (0..31)
        #pragma unroll
        for (int k = 0; k < 32; k++) {
            float hk = __shfl_sync(0xffffffffu, m0, k);
            acc += hk * sW2[k * 32 + lane];
        }
        #pragma unroll
        for (int k = 0; k < 32; k++) {
            float hk = __shfl_sync(0xffffffffu, m1v, k);
            acc += hk * sW2[(k + 32) * 32 + lane];
        }
        float p = acc * sW3[lane];             // no ReLU after W2 (matches ref)
        #pragma unroll
        for (int off = 16; off > 0; off >>= 1)
            p += __shfl_xor_sync(0xffffffffu, p, off);
        if (lane == 0) out[base + r] = p + sb3;
    }
}

// ---------------- launch ----------------------------------------------------
extern "C" void kernel_launch(void* const* d_in, const int* in_sizes, int n_in,
                              void* d_out, int out_size) {
    const int*   userIdx = (const int*)  d_in[0];
    const int*   itemIdx = (const int*)  d_in[1];
    const int*   lapRows = (const int*)  d_in[2];
    const int*   lapCols = (const int*)  d_in[3];
    const float* lapVals = (const float*)d_in[4];
    const float* uEmb    = (const float*)d_in[5];
    const float* iEmb    = (const float*)d_in[6];
    const float* gW0     = (const float*)d_in[7];
    const float* gb0     = (const float*)d_in[8];
    const float* gW1     = (const float*)d_in[9];
    const float* gb1     = (const float*)d_in[10];
    const float* W1      = (const float*)d_in[11];
    const float* b1      = (const float*)d_in[12];
    const float* W2      = (const float*)d_in[13];
    const float* b2      = (const float*)d_in[14];
    const float* W3      = (const float*)d_in[15];
    const float* b3      = (const float*)d_in[16];
    float* out = (float*)d_out;

    const int nnz = in_sizes[2];

    float *feat0, *feat1, *feat2;
    cudaGetSymbolAddress((void**)&feat0, g_feat0);
    cudaGetSymbolAddress((void**)&feat1, g_feat1);
    cudaGetSymbolAddress((void**)&feat2, g_feat2);

    // 1. feat0 = concat(uEmb, iEmb)
    init_feat_kernel<<<(N_NODES * 16 + 255) / 256, 256>>>((const float4*)uEmb,
                                                          (const float4*)iEmb);

    // 2. build CSR (histogram -> scan -> scatter); reused by both layers
    const int eb = (nnz + 255) / 256;
    zero_cnt_kernel<<<NB_SCAN, 256>>>();
    hist_kernel<<<eb, 256>>>(lapRows, nnz);
    scan1_kernel<<<NB_SCAN, 256>>>();
    scan2_kernel<<<1, 1024>>>();
    scan3_kernel<<<NB_SCAN, 256>>>(nnz);
    scatter_kernel<<<eb, 256>>>(lapRows, lapCols, lapVals, nnz);

    // 3. fused layers: feat_{k+1} = relu((L @ feat_k + feat_k) @ W + b)
    const int lb = (N_NODES + 31) / 32;   // 8 warps x 4 rows per block
    spmm_gemm_kernel<<<lb, 256>>>(feat0, gW0, gb0, feat1, N_NODES);
    spmm_gemm_kernel<<<lb, 256>>>(feat1, gW1, gb1, feat2, N_NODES);

    // 4. fused gather + 3-layer MLP
    mlp_fused_kernel<<<BATCH / 64, 256>>>(userIdx, itemIdx,
                                          W1, b1, W2, b2, W3, b3, out);
}